// round 3
// baseline (speedup 1.0000x reference)
#include <cuda_runtime.h>

#define NB 8
#define NV 2048
#define NP 32
#define NSH 16
#define NM 20
#define NS 4
#define BLOCKS_P1 2048   // 8 b * 256 blocks, each block = 8 warps = 8 v's

// Scratch (allocation-free rule: __device__ globals)
__device__ float g_partials[BLOCKS_P1 * 16];
__device__ __align__(16) float g_inv[NB * 16];   // [b][l][s], l*4+s

__device__ __forceinline__ void compute_monoms(float x, float y, float z, float* m) {
    float x2 = x * x, y2 = y * y, z2 = z * z;
    m[0]  = 1.0f;
    m[1]  = z;        m[2]  = z2;        m[3]  = z2 * z;
    m[4]  = y;        m[5]  = y * z;     m[6]  = y * z2;
    m[7]  = y2;       m[8]  = y2 * z;    m[9]  = y2 * y;
    m[10] = x;        m[11] = x * z;     m[12] = x * z2;
    m[13] = x * y;    m[14] = x * y * z; m[15] = x * y2;
    m[16] = x2;       m[17] = x2 * z;    m[18] = x2 * y;
    m[19] = x2 * x;
}

__device__ __forceinline__ void load_point(const float* __restrict__ patches, int base,
                                           float& d, float& x, float& y, float& z) {
    float px = patches[base + 0];
    float py = patches[base + 1];
    float pz = patches[base + 2];
    float d2 = fmaf(px, px, fmaf(py, py, pz * pz));
    d = sqrtf(d2);
    float rinv = 1.0f / fmaxf(d, 1e-6f);
    x = -px * rinv;
    y = -py * rinv;
    z = -pz * rinv;
}

__device__ __forceinline__ void compute_shells(float d, float* shn) {
    // rad_s = s/3; e = exp(-16 (d-rad)^2); normalize; mask d<=1
    float t0 = d;
    float t1 = d - (1.0f / 3.0f);
    float t2 = d - (2.0f / 3.0f);
    float t3 = d - 1.0f;
    float e0 = __expf(-16.0f * t0 * t0);
    float e1 = __expf(-16.0f * t1 * t1);
    float e2 = __expf(-16.0f * t2 * t2);
    float e3 = __expf(-16.0f * t3 * t3);
    float msk = (d <= 1.0f) ? 1.0f : 0.0f;
    float rs = msk / fmaxf(e0 + e1 + e2 + e3, 1e-6f);
    shn[0] = e0 * rs;
    shn[1] = e1 * rs;
    shn[2] = e2 * rs;
    shn[3] = e3 * rs;
}

// ---------------------------------------------------------------------------
// Pass 1: per-(b,v) reduction. warp = (b,v), lane = point p.
// c[l*4+s] = sum_p G_l(p) * shn_s(p)^2 ; sqrt ; block partial-sum over 8 v's.
// ---------------------------------------------------------------------------
__global__ void __launch_bounds__(256) pass1_kernel(const float* __restrict__ patches,
                                                    const float* __restrict__ Y) {
    __shared__ __align__(16) float Ys[NSH * NM];
    __shared__ float wpart[8][16];

    int tid = threadIdx.x;
    for (int t = tid; t < NSH * NM; t += 256) Ys[t] = Y[t];
    __syncthreads();

    int bi = blockIdx.x;
    int b = bi >> 8;                     // 256 blocks per b
    int wid = tid >> 5, lane = tid & 31;
    int v = (bi & 255) * 8 + wid;

    int bv = b * NV + v;
    int base = (bv * NP + lane) * 3;

    float d, x, y, z;
    load_point(patches, base, d, x, y, z);

    float m[NM];
    compute_monoms(x, y, z, m);

    const float4* Y4 = reinterpret_cast<const float4*>(Ys);
    float G[4] = {0.f, 0.f, 0.f, 0.f};
#pragma unroll
    for (int i = 0; i < NSH; i++) {
        float acc = 0.0f;
#pragma unroll
        for (int j = 0; j < 5; j++) {
            float4 yv = Y4[i * 5 + j];
            acc = fmaf(yv.x, m[4 * j + 0], acc);
            acc = fmaf(yv.y, m[4 * j + 1], acc);
            acc = fmaf(yv.z, m[4 * j + 2], acc);
            acc = fmaf(yv.w, m[4 * j + 3], acc);
        }
        int l = (i == 0) ? 0 : (i < 4) ? 1 : (i < 9) ? 2 : 3;
        G[l] = fmaf(acc, acc, G[l]);
    }

    float shn[NS];
    compute_shells(d, shn);
    float ws[NS];
#pragma unroll
    for (int s = 0; s < NS; s++) ws[s] = shn[s] * shn[s];

    float c[16];
#pragma unroll
    for (int l = 0; l < 4; l++)
#pragma unroll
        for (int s = 0; s < NS; s++) c[l * 4 + s] = G[l] * ws[s];

    // Full warp butterfly: after 5 stages every lane holds the sum over all
    // 32 points for every channel. Simple and correct.
#pragma unroll
    for (int k = 16; k > 0; k >>= 1) {
#pragma unroll
        for (int j = 0; j < 16; j++)
            c[j] += __shfl_xor_sync(0xFFFFFFFFu, c[j], k);
    }

    if (lane < 16) {
        float tot;
        switch (lane) {     // compile-time register pick per lane group
            case 0:  tot = c[0];  break;
            case 1:  tot = c[1];  break;
            case 2:  tot = c[2];  break;
            case 3:  tot = c[3];  break;
            case 4:  tot = c[4];  break;
            case 5:  tot = c[5];  break;
            case 6:  tot = c[6];  break;
            case 7:  tot = c[7];  break;
            case 8:  tot = c[8];  break;
            case 9:  tot = c[9];  break;
            case 10: tot = c[10]; break;
            case 11: tot = c[11]; break;
            case 12: tot = c[12]; break;
            case 13: tot = c[13]; break;
            case 14: tot = c[14]; break;
            default: tot = c[15]; break;
        }
        wpart[wid][lane] = sqrtf(tot);   // sqrt BEFORE mean over v
    }
    __syncthreads();

    if (tid < 16) {
        float s = 0.0f;
#pragma unroll
        for (int w = 0; w < 8; w++) s += wpart[w][tid];
        g_partials[bi * 16 + tid] = s;
    }
}

// ---------------------------------------------------------------------------
// Finalize: mean over v (256 block-partials per b), clamp, reciprocal.
// ---------------------------------------------------------------------------
__global__ void finalize_kernel() {
    int t = threadIdx.x;          // 128 threads = 8 b * 16 (l,s)
    int b = t >> 4, ls = t & 15;
    float s = 0.0f;
    for (int j = 0; j < 256; j++)
        s += g_partials[(b * 256 + j) * 16 + ls];
    float ml = s * (1.0f / 2048.0f);
    ml = fmaxf(ml, 1e-8f);
    g_inv[b * 16 + ls] = 1.0f / ml;
}

// ---------------------------------------------------------------------------
// Pass 2: recompute sh & shells, stage per-warp in smem, coalesced STG.128.
// ---------------------------------------------------------------------------
__global__ void __launch_bounds__(256) pass2_kernel(const float* __restrict__ patches,
                                                    const float* __restrict__ Y,
                                                    float* __restrict__ out) {
    __shared__ __align__(16) float Ys[NSH * NM];
    __shared__ float sh_s[8][NP * 17];     // pitch 17 floats -> conflict-free
    __shared__ float4 sc_s[8][NP];

    int tid = threadIdx.x;
    for (int t = tid; t < NSH * NM; t += 256) Ys[t] = Y[t];
    __syncthreads();

    int bi = blockIdx.x;
    int b = bi >> 8;
    int wid = tid >> 5, lane = tid & 31;
    int v = (bi & 255) * 8 + wid;

    int bv = b * NV + v;
    int base = (bv * NP + lane) * 3;

    float d, x, y, z;
    load_point(patches, base, d, x, y, z);

    float m[NM];
    compute_monoms(x, y, z, m);

    const float4* Y4 = reinterpret_cast<const float4*>(Ys);
#pragma unroll
    for (int i = 0; i < NSH; i++) {
        float acc = 0.0f;
#pragma unroll
        for (int j = 0; j < 5; j++) {
            float4 yv = Y4[i * 5 + j];
            acc = fmaf(yv.x, m[4 * j + 0], acc);
            acc = fmaf(yv.y, m[4 * j + 1], acc);
            acc = fmaf(yv.z, m[4 * j + 2], acc);
            acc = fmaf(yv.w, m[4 * j + 3], acc);
        }
        sh_s[wid][lane * 17 + i] = acc;
    }

    float shn[NS];
    compute_shells(d, shn);
    sc_s[wid][lane] = make_float4(shn[0], shn[1], shn[2], shn[3]);

    // per-lane fixed (i, l) for the write phase
    int myi = lane & 15;
    int myl = (myi == 0) ? 0 : (myi < 4) ? 1 : (myi < 9) ? 2 : 3;
    float4 inv4 = reinterpret_cast<const float4*>(g_inv)[b * 4 + myl];
    int half = lane >> 4;

    __syncwarp();

    // warp's output block: 32 points * 64 floats = 8KB contiguous.
    // iteration ci writes 512 contiguous bytes (32 lanes * float4):
    // float4 index n = ci*32 + lane = (2*ci+half)*16 + (lane&15) = q*16 + myi.
    float4* o = reinterpret_cast<float4*>(out) + bv * (NP * NSH);  // float4 units
#pragma unroll
    for (int ci = 0; ci < 16; ci++) {
        int q = 2 * ci + half;                 // point index within warp
        float4 s4 = sc_s[wid][q];
        float sh = sh_s[wid][q * 17 + myi];
        float4 r;
        r.x = sh * s4.x * inv4.x;
        r.y = sh * s4.y * inv4.y;
        r.z = sh * s4.z * inv4.z;
        r.w = sh * s4.w * inv4.w;
        o[ci * 32 + lane] = r;
    }
}

extern "C" void kernel_launch(void* const* d_in, const int* in_sizes, int n_in,
                              void* d_out, int out_size) {
    const float* patches = (const float*)d_in[0];
    const float* Y       = (const float*)d_in[1];
    float* out           = (float*)d_out;

    pass1_kernel<<<BLOCKS_P1, 256>>>(patches, Y);
    finalize_kernel<<<1, 128>>>();
    pass2_kernel<<<BLOCKS_P1, 256>>>(patches, Y, out);
}

// round 4
// speedup vs baseline: 1.1660x; 1.1660x over previous
#include <cuda_runtime.h>

#define NB 8
#define NV 2048
#define NP 32
#define NSH 16
#define NM 20
#define NS 4
#define BLOCKS 1024     // 8 b * 128 blocks; block = 8 warps * 2 v = 16 v

// Scratch (allocation-free rule: __device__ globals)
__device__ float g_partials[BLOCKS * 16];
__device__ __align__(16) float g_inv[NB * 16];   // [b][l][s], l*4+s

__device__ __forceinline__ void compute_monoms(float x, float y, float z, float* m) {
    float x2 = x * x, y2 = y * y, z2 = z * z;
    m[0]  = 1.0f;
    m[1]  = z;        m[2]  = z2;        m[3]  = z2 * z;
    m[4]  = y;        m[5]  = y * z;     m[6]  = y * z2;
    m[7]  = y2;       m[8]  = y2 * z;    m[9]  = y2 * y;
    m[10] = x;        m[11] = x * z;     m[12] = x * z2;
    m[13] = x * y;    m[14] = x * y * z; m[15] = x * y2;
    m[16] = x2;       m[17] = x2 * z;    m[18] = x2 * y;
    m[19] = x2 * x;
}

__device__ __forceinline__ void load_point(const float* __restrict__ patches, int base,
                                           float& d, float& x, float& y, float& z) {
    float px = patches[base + 0];
    float py = patches[base + 1];
    float pz = patches[base + 2];
    float d2 = fmaf(px, px, fmaf(py, py, pz * pz));
    d = sqrtf(d2);
    float rinv = 1.0f / fmaxf(d, 1e-6f);
    x = -px * rinv;
    y = -py * rinv;
    z = -pz * rinv;
}

__device__ __forceinline__ void compute_shells(float d, float* shn) {
    float t0 = d;
    float t1 = d - (1.0f / 3.0f);
    float t2 = d - (2.0f / 3.0f);
    float t3 = d - 1.0f;
    float e0 = __expf(-16.0f * t0 * t0);
    float e1 = __expf(-16.0f * t1 * t1);
    float e2 = __expf(-16.0f * t2 * t2);
    float e3 = __expf(-16.0f * t3 * t3);
    float msk = (d <= 1.0f) ? 1.0f : 0.0f;
    float rs = msk / fmaxf(e0 + e1 + e2 + e3, 1e-6f);
    shn[0] = e0 * rs;
    shn[1] = e1 * rs;
    shn[2] = e2 * rs;
    shn[3] = e3 * rs;
}

// ---------------------------------------------------------------------------
// Pass 1: warp = 2 v's, lane = point p of both. Per v: c[l,s] = sum_p G_l*ws_s,
// reduced via smem transpose (no butterfly), sqrt, block partial.
// ---------------------------------------------------------------------------
__global__ void __launch_bounds__(256) pass1_kernel(const float* __restrict__ patches,
                                                    const float* __restrict__ Y) {
    __shared__ __align__(16) float Ys[NSH * NM];
    __shared__ float red[8][584];        // per warp: vsel*292 + p*9 + c (c<8)
    __shared__ float wpart[8][2][16];

    int tid = threadIdx.x;
    for (int t = tid; t < NSH * NM; t += 256) Ys[t] = Y[t];
    __syncthreads();

    int bi = blockIdx.x;
    int b = bi >> 7;                       // 128 blocks per b
    int wid = tid >> 5, lane = tid & 31;
    int va = b * NV + (bi & 127) * 16 + wid * 2;   // even bv; warp covers va, va+1

    int base_a = (va * NP + lane) * 3;
    int base_b = base_a + NP * 3;

    float da, xa, ya, za, db, xb, yb, zb;
    load_point(patches, base_a, da, xa, ya, za);
    load_point(patches, base_b, db, xb, yb, zb);

    float ma[NM], mb[NM];
    compute_monoms(xa, ya, za, ma);
    compute_monoms(xb, yb, zb, mb);

    const float4* Y4 = reinterpret_cast<const float4*>(Ys);
    float Ga[4] = {0.f, 0.f, 0.f, 0.f};
    float Gb[4] = {0.f, 0.f, 0.f, 0.f};
#pragma unroll
    for (int i = 0; i < NSH; i++) {
        float aa = 0.0f, ab = 0.0f;
#pragma unroll
        for (int j = 0; j < 5; j++) {
            float4 yv = Y4[i * 5 + j];
            aa = fmaf(yv.x, ma[4 * j + 0], aa);
            aa = fmaf(yv.y, ma[4 * j + 1], aa);
            aa = fmaf(yv.z, ma[4 * j + 2], aa);
            aa = fmaf(yv.w, ma[4 * j + 3], aa);
            ab = fmaf(yv.x, mb[4 * j + 0], ab);
            ab = fmaf(yv.y, mb[4 * j + 1], ab);
            ab = fmaf(yv.z, mb[4 * j + 2], ab);
            ab = fmaf(yv.w, mb[4 * j + 3], ab);
        }
        int l = (i == 0) ? 0 : (i < 4) ? 1 : (i < 9) ? 2 : 3;
        Ga[l] = fmaf(aa, aa, Ga[l]);
        Gb[l] = fmaf(ab, ab, Gb[l]);
    }

    float sa[NS], sb[NS];
    compute_shells(da, sa);
    compute_shells(db, sb);

    // stash G[4], ws[4] per (vsel, p)
    {
        float* ra = &red[wid][lane * 9];
        float* rb = &red[wid][292 + lane * 9];
#pragma unroll
        for (int l = 0; l < 4; l++) { ra[l] = Ga[l]; rb[l] = Gb[l]; }
#pragma unroll
        for (int s = 0; s < 4; s++) { ra[4 + s] = sa[s] * sa[s]; rb[4 + s] = sb[s] * sb[s]; }
    }
    __syncwarp();

    // 32 reducer lanes: lane = vsel*16 + (l*4+s); sum over 32 points
    {
        int vsel = lane >> 4, ls = lane & 15, l = ls >> 2, s = ls & 3;
        const float* rr = &red[wid][vsel * 292];
        float t = 0.0f;
#pragma unroll
        for (int p = 0; p < 32; p++)
            t = fmaf(rr[p * 9 + l], rr[p * 9 + 4 + s], t);
        wpart[wid][vsel][ls] = sqrtf(t);   // sqrt BEFORE mean over v
    }
    __syncthreads();

    if (tid < 16) {
        float s = 0.0f;
#pragma unroll
        for (int w = 0; w < 8; w++)
#pragma unroll
            for (int vs = 0; vs < 2; vs++)
                s += wpart[w][vs][tid];
        g_partials[bi * 16 + tid] = s;     // sum over this block's 16 v
    }
}

// ---------------------------------------------------------------------------
// Finalize: mean over v (128 block-partials per b), clamp, reciprocal.
// ---------------------------------------------------------------------------
__global__ void finalize_kernel() {
    int t = threadIdx.x;          // 128 threads = 8 b * 16 (l,s)
    int b = t >> 4, ls = t & 15;
    float s = 0.0f;
    for (int j = 0; j < 128; j++)
        s += g_partials[(b * 128 + j) * 16 + ls];
    float ml = s * (1.0f / 2048.0f);
    ml = fmaxf(ml, 1e-8f);
    g_inv[b * 16 + ls] = 1.0f / ml;
}

// ---------------------------------------------------------------------------
// Pass 2: warp = 2 v's. Recompute sh & shells (Y LDS amortized over 2 points),
// stage in smem, then fully coalesced float4 store of 16KB per warp.
// ---------------------------------------------------------------------------
__global__ void __launch_bounds__(256) pass2_kernel(const float* __restrict__ patches,
                                                    const float* __restrict__ Y,
                                                    float* __restrict__ out) {
    __shared__ __align__(16) float Ys[NSH * NM];
    __shared__ float sh_s[8][1056];      // vsel*528 + i*33 + p
    __shared__ float4 sc_s[8][64];       // vsel*32 + p

    int tid = threadIdx.x;
    for (int t = tid; t < NSH * NM; t += 256) Ys[t] = Y[t];
    __syncthreads();

    int bi = blockIdx.x;
    int b = bi >> 7;
    int wid = tid >> 5, lane = tid & 31;
    int va = b * NV + (bi & 127) * 16 + wid * 2;

    int base_a = (va * NP + lane) * 3;
    int base_b = base_a + NP * 3;

    float da, xa, ya, za, db, xb, yb, zb;
    load_point(patches, base_a, da, xa, ya, za);
    load_point(patches, base_b, db, xb, yb, zb);

    float ma[NM], mb[NM];
    compute_monoms(xa, ya, za, ma);
    compute_monoms(xb, yb, zb, mb);

    const float4* Y4 = reinterpret_cast<const float4*>(Ys);
#pragma unroll
    for (int i = 0; i < NSH; i++) {
        float aa = 0.0f, ab = 0.0f;
#pragma unroll
        for (int j = 0; j < 5; j++) {
            float4 yv = Y4[i * 5 + j];
            aa = fmaf(yv.x, ma[4 * j + 0], aa);
            aa = fmaf(yv.y, ma[4 * j + 1], aa);
            aa = fmaf(yv.z, ma[4 * j + 2], aa);
            aa = fmaf(yv.w, ma[4 * j + 3], aa);
            ab = fmaf(yv.x, mb[4 * j + 0], ab);
            ab = fmaf(yv.y, mb[4 * j + 1], ab);
            ab = fmaf(yv.z, mb[4 * j + 2], ab);
            ab = fmaf(yv.w, mb[4 * j + 3], ab);
        }
        sh_s[wid][i * 33 + lane] = aa;
        sh_s[wid][528 + i * 33 + lane] = ab;
    }

    float sa[NS], sb[NS];
    compute_shells(da, sa);
    compute_shells(db, sb);
    sc_s[wid][lane]      = make_float4(sa[0], sa[1], sa[2], sa[3]);
    sc_s[wid][32 + lane] = make_float4(sb[0], sb[1], sb[2], sb[3]);

    int myi = lane & 15;
    int myl = (myi == 0) ? 0 : (myi < 4) ? 1 : (myi < 9) ? 2 : 3;
    float4 inv4 = reinterpret_cast<const float4*>(g_inv)[b * 4 + myl];
    int half = lane >> 4;

    __syncwarp();

    // warp's output: 2 v * 32 points * 16 float4 = 1024 contiguous float4.
    // n = ci*32+lane: vsel = n>>9 = ci>>4; q = (n>>4)&31 = 2*(ci&15)+half; myi = n&15.
    float4* o = reinterpret_cast<float4*>(out) + va * (NP * NSH);
#pragma unroll
    for (int ci = 0; ci < 32; ci++) {
        int vsel = ci >> 4;
        int q = 2 * (ci & 15) + half;
        float4 s4 = sc_s[wid][vsel * 32 + q];
        float sh = sh_s[wid][vsel * 528 + myi * 33 + q];
        float4 r;
        r.x = sh * s4.x * inv4.x;
        r.y = sh * s4.y * inv4.y;
        r.z = sh * s4.z * inv4.z;
        r.w = sh * s4.w * inv4.w;
        o[ci * 32 + lane] = r;
    }
}

extern "C" void kernel_launch(void* const* d_in, const int* in_sizes, int n_in,
                              void* d_out, int out_size) {
    const float* patches = (const float*)d_in[0];
    const float* Y       = (const float*)d_in[1];
    float* out           = (float*)d_out;

    pass1_kernel<<<BLOCKS, 256>>>(patches, Y);
    finalize_kernel<<<1, 128>>>();
    pass2_kernel<<<BLOCKS, 256>>>(patches, Y, out);
}